// round 4
// baseline (speedup 1.0000x reference)
#include <cuda_runtime.h>
#include <math.h>

#define BB 8
#define HH 96
#define WW 96
#define C0 256
#define HD 64
#define EPSV 1e-5f

// ---------------- scratch (no allocations allowed) ----------------
__device__ float g_x1[BB*HH*WW*HD];   // after coordconv+bn1+relu (NHWC)
__device__ float g_off[BB*HH*WW*18];  // offsets (NHWC, c=18)
__device__ float g_x2[BB*HH*WW*HD];   // after deform+bn2+relu
__device__ float g_x3[BB*HH*WW*HD];   // after r1+bn3+relu
__device__ float g_x4[BB*HH*WW*HD];   // after r2+bn4+relu

// =================================================================
// Kernel 1: coord_conv (258ic -> 64oc, 3x3, pad1) + BN1 + ReLU
// grid (3, 96, 8), block 256: 32 px * 8 oc-groups (8 oc each)
// =================================================================
__global__ void __launch_bounds__(256) k_coordconv(
    const float* __restrict__ feat, const float* __restrict__ w,
    const float* __restrict__ cb,
    const float* __restrict__ bg, const float* __restrict__ bbx,
    const float* __restrict__ bm, const float* __restrict__ bv)
{
    extern __shared__ float sm[];
    float* s_w     = sm;                       // [9][64][64] (tap, ic, oc)
    float* s_in    = s_w + 9*64*64;            // [3][64][35] (row, ic, px)
    float* s_cw    = s_in + 3*64*35;           // [9][2][64]
    float* s_scale = s_cw + 9*2*64;            // [64]
    float* s_shift = s_scale + 64;             // [64]

    int tid = threadIdx.x;
    int px  = tid & 31;
    int oc0 = (tid >> 5) * 8;
    int xb  = blockIdx.x * 32;
    int y   = blockIdx.y;
    int b   = blockIdx.z;

    float acc[8];
#pragma unroll
    for (int j = 0; j < 8; j++) acc[j] = 0.f;

    for (int chunk = 0; chunk < 4; chunk++) {
        __syncthreads();
        int ic0 = chunk * 64;
        for (int e = tid; e < 9*64*64; e += 256) {
            int oc  = e & 63;
            int ic  = (e >> 6) & 63;
            int tap = e >> 12;
            s_w[e] = w[((oc*258 + ic0 + ic)*3 + tap/3)*3 + (tap % 3)];
        }
        for (int e = tid; e < 3*34*64; e += 256) {
            int ic = e & 63;
            int p  = (e >> 6) % 34;
            int r  = e / (34*64);
            int gy = y + r - 1;
            int gx = xb + p - 1;
            float v = 0.f;
            if ((unsigned)gy < HH && (unsigned)gx < WW)
                v = feat[(((b*HH + gy)*WW + gx)*C0) + ic0 + ic];
            s_in[(r*64 + ic)*35 + p] = v;
        }
        __syncthreads();
#pragma unroll
        for (int ky = 0; ky < 3; ky++)
#pragma unroll
        for (int kx = 0; kx < 3; kx++) {
            const float* wr = s_w + (ky*3 + kx)*4096 + oc0;
            const float* ir = s_in + (ky*64)*35 + px + kx;
#pragma unroll 8
            for (int ic = 0; ic < 64; ic++) {
                float fin = ir[ic*35];
                float4 wa = *(const float4*)(wr + ic*64);
                float4 wb = *(const float4*)(wr + ic*64 + 4);
                acc[0] += fin*wa.x; acc[1] += fin*wa.y;
                acc[2] += fin*wa.z; acc[3] += fin*wa.w;
                acc[4] += fin*wb.x; acc[5] += fin*wb.y;
                acc[6] += fin*wb.z; acc[7] += fin*wb.w;
            }
        }
    }

    // coord-channel weights + BN params
    for (int e = tid; e < 9*2*64; e += 256) {
        int oc  = e & 63;
        int cc  = (e >> 6) & 1;
        int tap = e >> 7;
        s_cw[e] = w[((oc*258 + 256 + cc)*3 + tap/3)*3 + (tap % 3)];
    }
    if (tid < 64) {
        float inv = bg[tid] / sqrtf(bv[tid] + EPSV);
        s_scale[tid] = inv;
        s_shift[tid] = bbx[tid] - bm[tid]*inv;
    }
    __syncthreads();

    int x = xb + px;
#pragma unroll
    for (int tap = 0; tap < 9; tap++) {
        int gy = y + tap/3 - 1;
        int gx = x + tap%3 - 1;
        if ((unsigned)gy < HH && (unsigned)gx < WW) {
            float cx = -1.f + (float)gx * (2.f/95.f);   // channel 256 = xx
            float cy = -1.f + (float)gy * (2.f/95.f);   // channel 257 = yy
#pragma unroll
            for (int j = 0; j < 8; j++)
                acc[j] += s_cw[tap*128 + oc0 + j]*cx
                        + s_cw[tap*128 + 64 + oc0 + j]*cy;
        }
    }
    float* outp = g_x1 + (((b*HH + y)*WW + x)*HD) + oc0;
#pragma unroll
    for (int j = 0; j < 8; j++) {
        float t = (acc[j] + cb[oc0+j]) * s_scale[oc0+j] + s_shift[oc0+j];
        outp[j] = fmaxf(t, 0.f);
    }
}

// =================================================================
// Kernel 2: offset conv (64ic -> 18oc, 3x3, pad1, +bias)
// grid (3, 96, 8), block 288: 32 px * 9 groups (2 oc each)
// =================================================================
__global__ void __launch_bounds__(288) k_offconv(
    const float* __restrict__ w, const float* __restrict__ bias)
{
    extern __shared__ float sm[];
    float* s_w  = sm;                    // [9][64][18]
    float* s_in = s_w + 9*64*18;         // [3][64][35]
    float* s_b  = s_in + 3*64*35;        // [18]

    int tid = threadIdx.x;
    int px  = tid & 31;
    int oc0 = (tid >> 5) * 2;
    int xb  = blockIdx.x * 32;
    int y   = blockIdx.y;
    int b   = blockIdx.z;

    for (int e = tid; e < 9*64*18; e += 288) {
        int oc  = e % 18;
        int ic  = (e / 18) & 63;
        int tap = e / (18*64);
        s_w[e] = w[((oc*64 + ic)*3 + tap/3)*3 + (tap % 3)];
    }
    for (int e = tid; e < 3*34*64; e += 288) {
        int ic = e & 63;
        int p  = (e >> 6) % 34;
        int r  = e / (34*64);
        int gy = y + r - 1;
        int gx = xb + p - 1;
        float v = 0.f;
        if ((unsigned)gy < HH && (unsigned)gx < WW)
            v = g_x1[(((b*HH + gy)*WW + gx)*HD) + ic];
        s_in[(r*64 + ic)*35 + p] = v;
    }
    if (tid < 18) s_b[tid] = bias[tid];
    __syncthreads();

    float a0 = 0.f, a1 = 0.f;
#pragma unroll
    for (int ky = 0; ky < 3; ky++)
#pragma unroll
    for (int kx = 0; kx < 3; kx++) {
        const float* wr = s_w + (ky*3 + kx)*(64*18) + oc0;
        const float* ir = s_in + (ky*64)*35 + px + kx;
#pragma unroll 8
        for (int ic = 0; ic < 64; ic++) {
            float fin = ir[ic*35];
            float2 wv = *(const float2*)(wr + ic*18);
            a0 += fin*wv.x; a1 += fin*wv.y;
        }
    }
    int x = xb + px;
    float* outp = g_off + ((b*HH + y)*WW + x)*18 + oc0;
    outp[0] = a0 + s_b[oc0];
    outp[1] = a1 + s_b[oc0+1];
}

// =================================================================
// Kernel 3: deformable conv (64->64, K=9) + BN2 + ReLU
// grid (6, 96, 8): 16-px tiles. block 256.
// Phase A: bilinear gather -> s_acc[k][c][px]; Phase B: GEMM 576-K
// =================================================================
__global__ void __launch_bounds__(256) k_deform(
    const float* __restrict__ w,
    const float* __restrict__ bg, const float* __restrict__ bbx,
    const float* __restrict__ bm, const float* __restrict__ bv)
{
    extern __shared__ float sm[];
    float* s_w     = sm;                 // [9][64][64] (k, ic, oc)
    float* s_acc   = s_w + 9*64*64;      // [9][64][16] (k, c, px)
    float* s_scale = s_acc + 9*64*16;    // [64]
    float* s_shift = s_scale + 64;       // [64]

    int tid = threadIdx.x;
    int c   = tid & 63;
    int pg  = tid >> 6;                  // 0..3
    int xb  = blockIdx.x * 16;
    int y   = blockIdx.y;
    int b   = blockIdx.z;

    for (int e = tid; e < 9*64*64; e += 256) {
        int oc = e & 63;
        int ic = (e >> 6) & 63;
        int k  = e >> 12;
        s_w[e] = w[(oc*64 + ic)*9 + k];
    }
    if (tid < 64) {
        float inv = bg[tid] / sqrtf(bv[tid] + EPSV);
        s_scale[tid] = inv;
        s_shift[tid] = bbx[tid] - bm[tid]*inv;
    }

    const float* base = g_x1 + (size_t)b*HH*WW*HD + c;
    for (int i = 0; i < 4; i++) {
        int px = pg*4 + i;
        int x  = xb + px;
        const float* offp = g_off + ((b*HH + y)*WW + x)*18;
#pragma unroll
        for (int k = 0; k < 9; k++) {
            float py  = (float)(y + k/3 - 1) + offp[2*k];
            float pxf = (float)(x + k%3 - 1) + offp[2*k + 1];
            float fy0 = floorf(py), fx0 = floorf(pxf);
            int  iy = (int)fy0, ix = (int)fx0;
            float fy = py - fy0, fx = pxf - fx0;
            float a = 0.f;
            if ((unsigned)iy < HH) {
                const float* row = base + iy*(WW*HD);
                if ((unsigned)ix < WW)     a += row[ix*HD]     * (1.f-fy)*(1.f-fx);
                if ((unsigned)(ix+1) < WW) a += row[(ix+1)*HD] * (1.f-fy)*fx;
            }
            if ((unsigned)(iy+1) < HH) {
                const float* row = base + (iy+1)*(WW*HD);
                if ((unsigned)ix < WW)     a += row[ix*HD]     * fy*(1.f-fx);
                if ((unsigned)(ix+1) < WW) a += row[(ix+1)*HD] * fy*fx;
            }
            s_acc[(k*64 + c)*16 + px] = a;
        }
    }
    __syncthreads();

    // Phase B: thread handles oc=c, pixels pg*4..pg*4+3
    int oc = c;
    float4 acc = make_float4(0.f, 0.f, 0.f, 0.f);
#pragma unroll
    for (int k = 0; k < 9; k++) {
        const float* ar = s_acc + (k*64)*16 + pg*4;
        const float* wr = s_w + (k*64)*64 + oc;
#pragma unroll 4
        for (int ic = 0; ic < 64; ic++) {
            float4 av = *(const float4*)(ar + ic*16);
            float wv  = wr[ic*64];
            acc.x += av.x*wv; acc.y += av.y*wv;
            acc.z += av.z*wv; acc.w += av.w*wv;
        }
    }
    float sc = s_scale[oc], sh = s_shift[oc];
    float* outp = g_x2 + ((size_t)(b*HH + y)*WW + xb + pg*4)*HD + oc;
    outp[0]    = fmaxf(acc.x*sc + sh, 0.f);
    outp[HD]   = fmaxf(acc.y*sc + sh, 0.f);
    outp[2*HD] = fmaxf(acc.z*sc + sh, 0.f);
    outp[3*HD] = fmaxf(acc.w*sc + sh, 0.f);
}

// =================================================================
// Kernel 4/5: plain 3x3 conv 64->64 + BN + ReLU
// =================================================================
__global__ void __launch_bounds__(256) k_conv3(
    const float* __restrict__ in, float* __restrict__ out,
    const float* __restrict__ w,
    const float* __restrict__ bg, const float* __restrict__ bbx,
    const float* __restrict__ bm, const float* __restrict__ bv)
{
    extern __shared__ float sm[];
    float* s_w     = sm;                 // [9][64][64]
    float* s_in    = s_w + 9*64*64;      // [3][64][35]
    float* s_scale = s_in + 3*64*35;
    float* s_shift = s_scale + 64;

    int tid = threadIdx.x;
    int px  = tid & 31;
    int oc0 = (tid >> 5) * 8;
    int xb  = blockIdx.x * 32;
    int y   = blockIdx.y;
    int b   = blockIdx.z;

    for (int e = tid; e < 9*64*64; e += 256) {
        int oc  = e & 63;
        int ic  = (e >> 6) & 63;
        int tap = e >> 12;
        s_w[e] = w[((oc*64 + ic)*3 + tap/3)*3 + (tap % 3)];
    }
    for (int e = tid; e < 3*34*64; e += 256) {
        int ic = e & 63;
        int p  = (e >> 6) % 34;
        int r  = e / (34*64);
        int gy = y + r - 1;
        int gx = xb + p - 1;
        float v = 0.f;
        if ((unsigned)gy < HH && (unsigned)gx < WW)
            v = in[(((b*HH + gy)*WW + gx)*HD) + ic];
        s_in[(r*64 + ic)*35 + p] = v;
    }
    if (tid < 64) {
        float inv = bg[tid] / sqrtf(bv[tid] + EPSV);
        s_scale[tid] = inv;
        s_shift[tid] = bbx[tid] - bm[tid]*inv;
    }
    __syncthreads();

    float acc[8];
#pragma unroll
    for (int j = 0; j < 8; j++) acc[j] = 0.f;
#pragma unroll
    for (int ky = 0; ky < 3; ky++)
#pragma unroll
    for (int kx = 0; kx < 3; kx++) {
        const float* wr = s_w + (ky*3 + kx)*4096 + oc0;
        const float* ir = s_in + (ky*64)*35 + px + kx;
#pragma unroll 8
        for (int ic = 0; ic < 64; ic++) {
            float fin = ir[ic*35];
            float4 wa = *(const float4*)(wr + ic*64);
            float4 wb = *(const float4*)(wr + ic*64 + 4);
            acc[0] += fin*wa.x; acc[1] += fin*wa.y;
            acc[2] += fin*wa.z; acc[3] += fin*wa.w;
            acc[4] += fin*wb.x; acc[5] += fin*wb.y;
            acc[6] += fin*wb.z; acc[7] += fin*wb.w;
        }
    }
    int x = xb + px;
    float* outp = out + (((b*HH + y)*WW + x)*HD) + oc0;
#pragma unroll
    for (int j = 0; j < 8; j++)
        outp[j] = fmaxf(acc[j]*s_scale[oc0+j] + s_shift[oc0+j], 0.f);
}

// =================================================================
// Kernel 6: 1x1 conv (64->1) + sigmoid
// =================================================================
__global__ void __launch_bounds__(256) k_out(
    const float* __restrict__ ow, const float* __restrict__ ob,
    float* __restrict__ outp)
{
    __shared__ float sw[64];
    __shared__ float sb0;
    int tid = threadIdx.x;
    if (tid < 64) sw[tid] = ow[tid];
    if (tid == 0) sb0 = ob[0];
    __syncthreads();
    int p = blockIdx.x*256 + tid;
    if (p < BB*HH*WW) {
        const float4* xp = (const float4*)(g_x4 + (size_t)p*64);
        const float4* wp = (const float4*)sw;
        float a = 0.f;
#pragma unroll
        for (int i = 0; i < 16; i++) {
            float4 xv = xp[i], wv = wp[i];
            a += xv.x*wv.x + xv.y*wv.y + xv.z*wv.z + xv.w*wv.w;
        }
        outp[p] = 1.f / (1.f + expf(-(a + sb0)));
    }
}

// =================================================================
extern "C" void kernel_launch(void* const* d_in, const int* in_sizes, int n_in,
                              void* d_out, int out_size)
{
    const float* feat    = (const float*)d_in[0];
    const float* coord_w = (const float*)d_in[1];
    const float* coord_b = (const float*)d_in[2];
    const float* bn1_g   = (const float*)d_in[3];
    const float* bn1_b   = (const float*)d_in[4];
    const float* bn1_m   = (const float*)d_in[5];
    const float* bn1_v   = (const float*)d_in[6];
    const float* off_w   = (const float*)d_in[7];
    const float* off_b   = (const float*)d_in[8];
    const float* dc_w    = (const float*)d_in[9];
    const float* bn2_g   = (const float*)d_in[10];
    const float* bn2_b   = (const float*)d_in[11];
    const float* bn2_m   = (const float*)d_in[12];
    const float* bn2_v   = (const float*)d_in[13];
    const float* r1_w    = (const float*)d_in[14];
    const float* bn3_g   = (const float*)d_in[15];
    const float* bn3_b   = (const float*)d_in[16];
    const float* bn3_m   = (const float*)d_in[17];
    const float* bn3_v   = (const float*)d_in[18];
    const float* r2_w    = (const float*)d_in[19];
    const float* bn4_g   = (const float*)d_in[20];
    const float* bn4_b   = (const float*)d_in[21];
    const float* bn4_m   = (const float*)d_in[22];
    const float* bn4_v   = (const float*)d_in[23];
    const float* out_w   = (const float*)d_in[24];
    const float* out_b   = (const float*)d_in[25];
    float* out = (float*)d_out;

    const int SM1 = (9*64*64 + 3*64*35 + 9*2*64 + 128) * 4;   // 179456
    const int SMC = (9*64*64 + 3*64*35 + 128) * 4;            // 174848
    const int SMO = (9*64*18 + 3*64*35 + 32) * 4;             // 68480
    const int SMD = (9*64*64 + 9*64*16 + 128) * 4;            // 184832

    cudaFuncSetAttribute(k_coordconv, cudaFuncAttributeMaxDynamicSharedMemorySize, SM1);
    cudaFuncSetAttribute(k_offconv,   cudaFuncAttributeMaxDynamicSharedMemorySize, SMO);
    cudaFuncSetAttribute(k_deform,    cudaFuncAttributeMaxDynamicSharedMemorySize, SMD);
    cudaFuncSetAttribute(k_conv3,     cudaFuncAttributeMaxDynamicSharedMemorySize, SMC);

    void *px2 = nullptr, *px3 = nullptr, *px4 = nullptr;
    cudaGetSymbolAddress(&px2, g_x2);
    cudaGetSymbolAddress(&px3, g_x3);
    cudaGetSymbolAddress(&px4, g_x4);

    dim3 g32(3, 96, 8);
    k_coordconv<<<g32, 256, SM1>>>(feat, coord_w, coord_b,
                                   bn1_g, bn1_b, bn1_m, bn1_v);
    k_offconv<<<g32, 288, SMO>>>(off_w, off_b);
    k_deform<<<dim3(6, 96, 8), 256, SMD>>>(dc_w, bn2_g, bn2_b, bn2_m, bn2_v);
    k_conv3<<<g32, 256, SMC>>>((const float*)px2, (float*)px3, r1_w,
                               bn3_g, bn3_b, bn3_m, bn3_v);
    k_conv3<<<g32, 256, SMC>>>((const float*)px3, (float*)px4, r2_w,
                               bn4_g, bn4_b, bn4_m, bn4_v);
    k_out<<<288, 256>>>(out_w, out_b, out);
}

// round 8
// speedup vs baseline: 3.2091x; 3.2091x over previous
#include <cuda_runtime.h>
#include <math.h>

#define BB 8
#define HH 96
#define WW 96
#define C0 256
#define HD 64
#define EPSV 1e-5f

typedef unsigned long long ull;

// ---------------- scratch (no allocations allowed) ----------------
__device__ float g_x1[BB*HH*WW*HD];   // after coordconv+bn1+relu (NHWC)
__device__ float g_off[BB*HH*WW*18];  // offsets (NHWC, c=18)
__device__ float g_x2[BB*HH*WW*HD];   // after deform+bn2+relu
__device__ float g_x3[BB*HH*WW*HD];   // after r1+bn3+relu
__device__ float g_x4[BB*HH*WW*HD];   // after r2+bn4+relu

// transposed weights [tap][ic][oc]
__device__ float g_wc[9*258*64];      // coord_w
__device__ float g_w1[9*64*64];       // r1_w
__device__ float g_w2[9*64*64];       // r2_w
__device__ float g_wd[9*64*64];       // dc_w ([k][ic][oc])
__device__ float g_wo[9*64*18];       // off_w

// ---------------- f32x2 helpers ----------------
__device__ __forceinline__ void ffma2(ull &d, ull a, ull b) {
    asm("fma.rn.f32x2 %0, %1, %2, %0;" : "+l"(d) : "l"(a), "l"(b));
}
__device__ __forceinline__ ull rep2(float v) {
    unsigned u = __float_as_uint(v);
    ull r;
    asm("mov.b64 %0, {%1, %1};" : "=l"(r) : "r"(u));
    return r;
}
__device__ __forceinline__ float lo2(ull u) { return __uint_as_float((unsigned)u); }
__device__ __forceinline__ float hi2(ull u) { return __uint_as_float((unsigned)(u >> 32)); }

// =================================================================
// weight transpose prep (runs once per launch, cheap)
// =================================================================
__global__ void k_prep(const float* __restrict__ cw, const float* __restrict__ r1,
                       const float* __restrict__ r2, const float* __restrict__ dc,
                       const float* __restrict__ ow)
{
    int i = blockIdx.x*256 + threadIdx.x;
    if (i < 9*258*64) {
        int oc = i & 63; int ic = (i >> 6) % 258; int tap = i / (258*64);
        g_wc[i] = cw[(oc*258 + ic)*9 + tap];
    }
    if (i < 9*64*64) {
        int oc = i & 63; int ic = (i >> 6) & 63; int tap = i >> 12;
        g_w1[i] = r1[(oc*64 + ic)*9 + tap];
        g_w2[i] = r2[(oc*64 + ic)*9 + tap];
        g_wd[i] = dc[(oc*64 + ic)*9 + tap];
    }
    if (i < 9*64*18) {
        int oc = i % 18; int ic = (i/18) & 63; int tap = i / (18*64);
        g_wo[i] = ow[(oc*64 + ic)*9 + tap];
    }
}

// ---------------- shared loaders ----------------
// s_in layout: [3 rows][32 ic][99] (stride 99 for conflict-free)
__device__ __forceinline__ void load_tile_in(
    const float* __restrict__ gsrc, int Cstride, int ic0,
    float* s_in, int y, int b, int tid, int nthreads)
{
    for (int e = tid; e < 3*98*32; e += nthreads) {
        int ic = e & 31;
        int p  = (e >> 5) % 98;
        int r  = e / (98*32);
        int gy = y + r - 1, gx = p - 1;
        float v = 0.f;
        if ((unsigned)gy < HH && (unsigned)gx < WW)
            v = gsrc[((b*HH + gy)*WW + gx)*Cstride + ic0 + ic];
        s_in[(r*32 + ic)*99 + p] = v;
    }
}

// s_w layout: [9 tap][32 ic][64 oc]; gw layout [9][ICTOT][64]
__device__ __forceinline__ void load_tile_w(
    const float* __restrict__ gw, int ICTOT, int ic0,
    float* s_w, int tid, int nthreads)
{
    const int N4 = 9*32*64/4;  // 4608 float4
    for (int e = tid; e < N4; e += nthreads) {
        int oc4 = (e & 15) * 4;            // 16 float4 per ic
        int ic  = (e >> 4) & 31;
        int tap = e >> 9;
        *(float4*)(s_w + (tap*32 + ic)*64 + oc4) =
            *(const float4*)(gw + (tap*ICTOT + ic0 + ic)*64 + oc4);
    }
}

// ---------------- core 32-ic accumulation: 3px x 8oc (4 pairs) ----------------
__device__ __forceinline__ void conv_accum32(
    const float* s_w, const float* s_in, int l, int oc0, ull acc[3][4])
{
    for (int ic = 0; ic < 32; ic++) {
        ull rf[3][5];
#pragma unroll
        for (int r = 0; r < 3; r++) {
            const float* fp = s_in + (r*32 + ic)*99 + 3*l;
#pragma unroll
            for (int t = 0; t < 5; t++) rf[r][t] = rep2(fp[t]);
        }
#pragma unroll
        for (int ky = 0; ky < 3; ky++)
#pragma unroll
        for (int kx = 0; kx < 3; kx++) {
            const ulonglong2* wp =
                (const ulonglong2*)(s_w + ((ky*3 + kx)*32 + ic)*64 + oc0);
            ulonglong2 wA = wp[0];
            ulonglong2 wB = wp[1];
#pragma unroll
            for (int p = 0; p < 3; p++) {
                ull f = rf[ky][p + kx];
                ffma2(acc[p][0], f, wA.x);
                ffma2(acc[p][1], f, wA.y);
                ffma2(acc[p][2], f, wB.x);
                ffma2(acc[p][3], f, wB.y);
            }
        }
    }
}

// =================================================================
// coord_conv: 258ic -> 64oc, 3x3, +bias, BN1, ReLU. grid (96, 8), block 256
// smem: s_w 73728B + s_in 38016B + 512B = 112256B -> 2 CTAs/SM
// =================================================================
__global__ void __launch_bounds__(256, 2) k_coordn(
    const float* __restrict__ feat, const float* __restrict__ cb,
    const float* __restrict__ bg, const float* __restrict__ bbx,
    const float* __restrict__ bm, const float* __restrict__ bv)
{
    extern __shared__ float sm[];
    float* s_w     = sm;              // [9][32][64] (reused as s_cw in tail)
    float* s_in    = s_w + 9*32*64;   // [3][32][99]
    float* s_scale = s_in + 3*32*99;  // [64]
    float* s_shift = s_scale + 64;    // [64]

    int tid = threadIdx.x;
    int l   = tid & 31;
    int w   = tid >> 5;
    int oc0 = w * 8;
    int y   = blockIdx.x;
    int b   = blockIdx.y;

    if (tid < 64) {
        float inv = bg[tid] / sqrtf(bv[tid] + EPSV);
        s_scale[tid] = inv;
        s_shift[tid] = cb[tid]*inv + (bbx[tid] - bm[tid]*inv);
    }

    ull acc[3][4];
#pragma unroll
    for (int p = 0; p < 3; p++)
#pragma unroll
    for (int j = 0; j < 4; j++) acc[p][j] = 0ULL;

    for (int chunk = 0; chunk < 8; chunk++) {
        __syncthreads();
        load_tile_w(g_wc, 258, chunk*32, s_w, tid, 256);
        load_tile_in(feat, C0, chunk*32, s_in, y, b, tid, 256);
        __syncthreads();
        conv_accum32(s_w, s_in, l, oc0, acc);
    }

    // tail: coord channels (ic 256=xx, 257=yy) — reuse s_w space
    __syncthreads();
    float* s_cw = s_w;   // [9][2][64]
    for (int e = tid; e < 9*2*64; e += 256) {
        int oc  = e & 63;
        int cc  = (e >> 6) & 1;
        int tap = e >> 7;
        s_cw[e] = g_wc[(tap*258 + 256 + cc)*64 + oc];
    }
    __syncthreads();

#pragma unroll
    for (int p = 0; p < 3; p++) {
        int px = 3*l + p;
        float a[8];
        a[0]=lo2(acc[p][0]); a[1]=hi2(acc[p][0]);
        a[2]=lo2(acc[p][1]); a[3]=hi2(acc[p][1]);
        a[4]=lo2(acc[p][2]); a[5]=hi2(acc[p][2]);
        a[6]=lo2(acc[p][3]); a[7]=hi2(acc[p][3]);
#pragma unroll
        for (int tap = 0; tap < 9; tap++) {
            int gy = y + tap/3 - 1;
            int gx = px + tap%3 - 1;
            if ((unsigned)gy < HH && (unsigned)gx < WW) {
                float cx = -1.f + (float)gx * (2.f/95.f);  // ic 256
                float cy = -1.f + (float)gy * (2.f/95.f);  // ic 257
#pragma unroll
                for (int j = 0; j < 8; j++)
                    a[j] += s_cw[tap*128 + oc0 + j]*cx
                          + s_cw[tap*128 + 64 + oc0 + j]*cy;
            }
        }
        float o[8];
#pragma unroll
        for (int j = 0; j < 8; j++)
            o[j] = fmaxf(a[j]*s_scale[oc0+j] + s_shift[oc0+j], 0.f);
        float* outp = g_x1 + ((b*HH + y)*WW + px)*HD + oc0;
        *(float4*)outp       = make_float4(o[0], o[1], o[2], o[3]);
        *(float4*)(outp + 4) = make_float4(o[4], o[5], o[6], o[7]);
    }
}

// =================================================================
// plain 3x3 conv 64->64 + BN + ReLU. grid (96, 8), block 256
// =================================================================
__global__ void __launch_bounds__(256, 2) k_conv3n(
    const float* __restrict__ in, float* __restrict__ out,
    const float* __restrict__ gw,
    const float* __restrict__ bg, const float* __restrict__ bbx,
    const float* __restrict__ bm, const float* __restrict__ bv)
{
    extern __shared__ float sm[];
    float* s_w     = sm;
    float* s_in    = s_w + 9*32*64;
    float* s_scale = s_in + 3*32*99;
    float* s_shift = s_scale + 64;

    int tid = threadIdx.x;
    int l   = tid & 31;
    int w   = tid >> 5;
    int oc0 = w * 8;
    int y   = blockIdx.x;
    int b   = blockIdx.y;

    if (tid < 64) {
        float inv = bg[tid] / sqrtf(bv[tid] + EPSV);
        s_scale[tid] = inv;
        s_shift[tid] = bbx[tid] - bm[tid]*inv;
    }

    ull acc[3][4];
#pragma unroll
    for (int p = 0; p < 3; p++)
#pragma unroll
    for (int j = 0; j < 4; j++) acc[p][j] = 0ULL;

    for (int chunk = 0; chunk < 2; chunk++) {
        __syncthreads();
        load_tile_w(gw, 64, chunk*32, s_w, tid, 256);
        load_tile_in(in, HD, chunk*32, s_in, y, b, tid, 256);
        __syncthreads();
        conv_accum32(s_w, s_in, l, oc0, acc);
    }

#pragma unroll
    for (int p = 0; p < 3; p++) {
        int px = 3*l + p;
        float a[8];
        a[0]=lo2(acc[p][0]); a[1]=hi2(acc[p][0]);
        a[2]=lo2(acc[p][1]); a[3]=hi2(acc[p][1]);
        a[4]=lo2(acc[p][2]); a[5]=hi2(acc[p][2]);
        a[6]=lo2(acc[p][3]); a[7]=hi2(acc[p][3]);
        float o[8];
#pragma unroll
        for (int j = 0; j < 8; j++)
            o[j] = fmaxf(a[j]*s_scale[oc0+j] + s_shift[oc0+j], 0.f);
        float* outp = out + ((b*HH + y)*WW + px)*HD + oc0;
        *(float4*)outp       = make_float4(o[0], o[1], o[2], o[3]);
        *(float4*)(outp + 4) = make_float4(o[4], o[5], o[6], o[7]);
    }
}

// =================================================================
// offset conv: 64ic -> 18oc, 3x3, +bias. grid (96, 8), block 288
// warp w handles oc {2w, 2w+1}; lane: 3 px. scalar FFMA.
// =================================================================
__global__ void __launch_bounds__(288, 2) k_offc(const float* __restrict__ bias)
{
    extern __shared__ float sm[];
    float* s_w  = sm;               // [9][32][18] = 5184
    float* s_in = s_w + 9*32*18;    // [3][32][99]

    int tid = threadIdx.x;
    int l   = tid & 31;
    int w   = tid >> 5;             // 0..8
    int y   = blockIdx.x;
    int b   = blockIdx.y;

    float acc[3][2];
#pragma unroll
    for (int p = 0; p < 3; p++) { acc[p][0] = 0.f; acc[p][1] = 0.f; }

    for (int chunk = 0; chunk < 2; chunk++) {
        __syncthreads();
        for (int e = tid; e < 9*32*18; e += 288) {
            int tap = e / 576;
            int rem = e % 576;          // ic*18 + oc
            s_w[e] = g_wo[tap*1152 + chunk*32*18 + rem];
        }
        load_tile_in(g_x1, HD, chunk*32, s_in, y, b, tid, 288);
        __syncthreads();

        for (int ic = 0; ic < 32; ic++) {
            float f[3][5];
#pragma unroll
            for (int r = 0; r < 3; r++) {
                const float* fp = s_in + (r*32 + ic)*99 + 3*l;
#pragma unroll
                for (int t = 0; t < 5; t++) f[r][t] = fp[t];
            }
#pragma unroll
            for (int ky = 0; ky < 3; ky++)
#pragma unroll
            for (int kx = 0; kx < 3; kx++) {
                float2 wv = *(const float2*)(s_w + ((ky*3+kx)*32 + ic)*18 + 2*w);
#pragma unroll
                for (int p = 0; p < 3; p++) {
                    acc[p][0] += f[ky][p+kx]*wv.x;
                    acc[p][1] += f[ky][p+kx]*wv.y;
                }
            }
        }
    }

    float b0 = __ldg(&bias[2*w]);
    float b1 = __ldg(&bias[2*w + 1]);
#pragma unroll
    for (int p = 0; p < 3; p++) {
        int px = 3*l + p;
        float2 o = make_float2(acc[p][0] + b0, acc[p][1] + b1);
        *(float2*)(g_off + ((b*HH + y)*WW + px)*18 + 2*w) = o;
    }
}

// =================================================================
// deformable conv (64->64, K=9) + BN2 + ReLU — unchanged structure,
// weight load now coalesced from pre-transposed g_wd
// =================================================================
__global__ void __launch_bounds__(256) k_deform(
    const float* __restrict__ bg, const float* __restrict__ bbx,
    const float* __restrict__ bm, const float* __restrict__ bv)
{
    extern __shared__ float sm[];
    float* s_w     = sm;                 // [9][64][64] (k, ic, oc)
    float* s_acc   = s_w + 9*64*64;      // [9][64][16] (k, c, px)
    float* s_scale = s_acc + 9*64*16;    // [64]
    float* s_shift = s_scale + 64;       // [64]

    int tid = threadIdx.x;
    int c   = tid & 63;
    int pg  = tid >> 6;                  // 0..3
    int xb  = blockIdx.x * 16;
    int y   = blockIdx.y;
    int b   = blockIdx.z;

    for (int e = tid; e < 9*64*64/4; e += 256)
        ((float4*)s_w)[e] = ((const float4*)g_wd)[e];
    if (tid < 64) {
        float inv = bg[tid] / sqrtf(bv[tid] + EPSV);
        s_scale[tid] = inv;
        s_shift[tid] = bbx[tid] - bm[tid]*inv;
    }

    const float* base = g_x1 + (size_t)b*HH*WW*HD + c;
    for (int i = 0; i < 4; i++) {
        int px = pg*4 + i;
        int x  = xb + px;
        const float* offp = g_off + ((b*HH + y)*WW + x)*18;
#pragma unroll
        for (int k = 0; k < 9; k++) {
            float py  = (float)(y + k/3 - 1) + offp[2*k];
            float pxf = (float)(x + k%3 - 1) + offp[2*k + 1];
            float fy0 = floorf(py), fx0 = floorf(pxf);
            int  iy = (int)fy0, ix = (int)fx0;
            float fy = py - fy0, fx = pxf - fx0;
            float a = 0.f;
            if ((unsigned)iy < HH) {
                const float* row = base + iy*(WW*HD);
                if ((unsigned)ix < WW)     a += row[ix*HD]     * (1.f-fy)*(1.f-fx);
                if ((unsigned)(ix+1) < WW) a += row[(ix+1)*HD] * (1.f-fy)*fx;
            }
            if ((unsigned)(iy+1) < HH) {
                const float* row = base + (iy+1)*(WW*HD);
                if ((unsigned)ix < WW)     a += row[ix*HD]     * fy*(1.f-fx);
                if ((unsigned)(ix+1) < WW) a += row[(ix+1)*HD] * fy*fx;
            }
            s_acc[(k*64 + c)*16 + px] = a;
        }
    }
    __syncthreads();

    int oc = c;
    float4 acc = make_float4(0.f, 0.f, 0.f, 0.f);
#pragma unroll
    for (int k = 0; k < 9; k++) {
        const float* ar = s_acc + (k*64)*16 + pg*4;
        const float* wr = s_w + (k*64)*64 + oc;
#pragma unroll 4
        for (int ic = 0; ic < 64; ic++) {
            float4 av = *(const float4*)(ar + ic*16);
            float wv  = wr[ic*64];
            acc.x += av.x*wv; acc.y += av.y*wv;
            acc.z += av.z*wv; acc.w += av.w*wv;
        }
    }
    float sc = s_scale[oc], sh = s_shift[oc];
    float* outp = g_x2 + ((size_t)(b*HH + y)*WW + xb + pg*4)*HD + oc;
    outp[0]    = fmaxf(acc.x*sc + sh, 0.f);
    outp[HD]   = fmaxf(acc.y*sc + sh, 0.f);
    outp[2*HD] = fmaxf(acc.z*sc + sh, 0.f);
    outp[3*HD] = fmaxf(acc.w*sc + sh, 0.f);
}

// =================================================================
// 1x1 conv (64->1) + sigmoid
// =================================================================
__global__ void __launch_bounds__(256) k_out(
    const float* __restrict__ ow, const float* __restrict__ ob,
    float* __restrict__ outp)
{
    __shared__ float sw[64];
    __shared__ float sb0;
    int tid = threadIdx.x;
    if (tid < 64) sw[tid] = ow[tid];
    if (tid == 0) sb0 = ob[0];
    __syncthreads();
    int p = blockIdx.x*256 + tid;
    if (p < BB*HH*WW) {
        const float4* xp = (const float4*)(g_x4 + (size_t)p*64);
        const float4* wp = (const float4*)sw;
        float a = 0.f;
#pragma unroll
        for (int i = 0; i < 16; i++) {
            float4 xv = xp[i], wv = wp[i];
            a += xv.x*wv.x + xv.y*wv.y + xv.z*wv.z + xv.w*wv.w;
        }
        outp[p] = 1.f / (1.f + expf(-(a + sb0)));
    }
}

// =================================================================
extern "C" void kernel_launch(void* const* d_in, const int* in_sizes, int n_in,
                              void* d_out, int out_size)
{
    const float* feat    = (const float*)d_in[0];
    const float* coord_w = (const float*)d_in[1];
    const float* coord_b = (const float*)d_in[2];
    const float* bn1_g   = (const float*)d_in[3];
    const float* bn1_b   = (const float*)d_in[4];
    const float* bn1_m   = (const float*)d_in[5];
    const float* bn1_v   = (const float*)d_in[6];
    const float* off_w   = (const float*)d_in[7];
    const float* off_b   = (const float*)d_in[8];
    const float* dc_w    = (const float*)d_in[9];
    const float* bn2_g   = (const float*)d_in[10];
    const float* bn2_b   = (const float*)d_in[11];
    const float* bn2_m   = (const float*)d_in[12];
    const float* bn2_v   = (const float*)d_in[13];
    const float* r1_w    = (const float*)d_in[14];
    const float* bn3_g   = (const float*)d_in[15];
    const float* bn3_b   = (const float*)d_in[16];
    const float* bn3_m   = (const float*)d_in[17];
    const float* bn3_v   = (const float*)d_in[18];
    const float* r2_w    = (const float*)d_in[19];
    const float* bn4_g   = (const float*)d_in[20];
    const float* bn4_b   = (const float*)d_in[21];
    const float* bn4_m   = (const float*)d_in[22];
    const float* bn4_v   = (const float*)d_in[23];
    const float* out_w   = (const float*)d_in[24];
    const float* out_b   = (const float*)d_in[25];
    float* out = (float*)d_out;

    const int SM_CONV = (9*32*64 + 3*32*99 + 128) * 4;   // 112256
    const int SM_OFF  = (9*32*18 + 3*32*99) * 4;         // 58752
    const int SMD     = (9*64*64 + 9*64*16 + 128) * 4;   // 184832

    cudaFuncSetAttribute(k_coordn, cudaFuncAttributeMaxDynamicSharedMemorySize, SM_CONV);
    cudaFuncSetAttribute(k_conv3n, cudaFuncAttributeMaxDynamicSharedMemorySize, SM_CONV);
    cudaFuncSetAttribute(k_offc,   cudaFuncAttributeMaxDynamicSharedMemorySize, SM_OFF);
    cudaFuncSetAttribute(k_deform, cudaFuncAttributeMaxDynamicSharedMemorySize, SMD);

    void *px2 = nullptr, *px3 = nullptr, *px4 = nullptr;
    cudaGetSymbolAddress(&px2, g_x2);
    cudaGetSymbolAddress(&px3, g_x3);
    cudaGetSymbolAddress(&px4, g_x4);
    void *pw1 = nullptr, *pw2 = nullptr;
    cudaGetSymbolAddress(&pw1, g_w1);
    cudaGetSymbolAddress(&pw2, g_w2);

    k_prep<<<581, 256>>>(coord_w, r1_w, r2_w, dc_w, off_w);

    dim3 gRow(96, 8);
    k_coordn<<<gRow, 256, SM_CONV>>>(feat, coord_b, bn1_g, bn1_b, bn1_m, bn1_v);
    k_offc<<<gRow, 288, SM_OFF>>>(off_b);
    k_deform<<<dim3(6, 96, 8), 256, SMD>>>(bn2_g, bn2_b, bn2_m, bn2_v);
    k_conv3n<<<gRow, 256, SM_CONV>>>((const float*)px2, (float*)px3,
                                     (const float*)pw1, bn3_g, bn3_b, bn3_m, bn3_v);
    k_conv3n<<<gRow, 256, SM_CONV>>>((const float*)px3, (float*)px4,
                                     (const float*)pw2, bn4_g, bn4_b, bn4_m, bn4_v);
    k_out<<<288, 256>>>(out_w, out_b, out);
}

// round 9
// speedup vs baseline: 3.8194x; 1.1902x over previous
#include <cuda_runtime.h>
#include <math.h>

#define BB 8
#define HH 96
#define WW 96
#define C0 256
#define HD 64
#define EPSV 1e-5f

typedef unsigned long long ull;

// ---------------- scratch (no allocations allowed) ----------------
__device__ float g_x1[BB*HH*WW*HD];   // after coordconv+bn1+relu (NHWC)
__device__ float g_off[BB*HH*WW*18];  // offsets (NHWC, c=18)
__device__ float g_x2[BB*HH*WW*HD];   // after deform+bn2+relu
__device__ float g_x3[BB*HH*WW*HD];   // after r1+bn3+relu
__device__ float g_x4[BB*HH*WW*HD];   // after r2+bn4+relu

// transposed weights [tap][ic][oc]
__device__ float g_wc[9*258*64];      // coord_w
__device__ float g_w1[9*64*64];       // r1_w
__device__ float g_w2[9*64*64];       // r2_w
__device__ float g_wd[9*64*64];       // dc_w ([k][ic][oc])
__device__ float g_wo[9*64*18];       // off_w

// ---------------- f32x2 helpers ----------------
__device__ __forceinline__ void ffma2(ull &d, ull a, ull b) {
    asm("fma.rn.f32x2 %0, %1, %2, %0;" : "+l"(d) : "l"(a), "l"(b));
}
__device__ __forceinline__ ull rep2(float v) {
    unsigned u = __float_as_uint(v);
    ull r;
    asm("mov.b64 %0, {%1, %1};" : "=l"(r) : "r"(u));
    return r;
}
__device__ __forceinline__ float lo2(ull u) { return __uint_as_float((unsigned)u); }
__device__ __forceinline__ float hi2(ull u) { return __uint_as_float((unsigned)(u >> 32)); }

// =================================================================
// weight transpose prep (runs once per launch, cheap)
// =================================================================
__global__ void k_prep(const float* __restrict__ cw, const float* __restrict__ r1,
                       const float* __restrict__ r2, const float* __restrict__ dc,
                       const float* __restrict__ ow)
{
    int i = blockIdx.x*256 + threadIdx.x;
    if (i < 9*258*64) {
        int oc = i & 63; int ic = (i >> 6) % 258; int tap = i / (258*64);
        g_wc[i] = cw[(oc*258 + ic)*9 + tap];
    }
    if (i < 9*64*64) {
        int oc = i & 63; int ic = (i >> 6) & 63; int tap = i >> 12;
        g_w1[i] = r1[(oc*64 + ic)*9 + tap];
        g_w2[i] = r2[(oc*64 + ic)*9 + tap];
        g_wd[i] = dc[(oc*64 + ic)*9 + tap];
    }
    if (i < 9*64*18) {
        int oc = i % 18; int ic = (i/18) & 63; int tap = i / (18*64);
        g_wo[i] = ow[(oc*64 + ic)*9 + tap];
    }
}

// ---------------- shared loaders ----------------
// s_in layout: [3 rows][32 ic][99] (stride 99 for conflict-free)
__device__ __forceinline__ void load_tile_in(
    const float* __restrict__ gsrc, int Cstride, int ic0,
    float* s_in, int y, int b, int tid, int nthreads)
{
    for (int e = tid; e < 3*98*32; e += nthreads) {
        int ic = e & 31;
        int p  = (e >> 5) % 98;
        int r  = e / (98*32);
        int gy = y + r - 1, gx = p - 1;
        float v = 0.f;
        if ((unsigned)gy < HH && (unsigned)gx < WW)
            v = gsrc[((b*HH + gy)*WW + gx)*Cstride + ic0 + ic];
        s_in[(r*32 + ic)*99 + p] = v;
    }
}

// s_w layout: [9 tap][32 ic][64 oc]; gw layout [9][ICTOT][64]
__device__ __forceinline__ void load_tile_w(
    const float* __restrict__ gw, int ICTOT, int ic0,
    float* s_w, int tid, int nthreads)
{
    const int N4 = 9*32*64/4;  // 4608 float4
    for (int e = tid; e < N4; e += nthreads) {
        int oc4 = (e & 15) * 4;            // 16 float4 per ic
        int ic  = (e >> 4) & 31;
        int tap = e >> 9;
        *(float4*)(s_w + (tap*32 + ic)*64 + oc4) =
            *(const float4*)(gw + (tap*ICTOT + ic0 + ic)*64 + oc4);
    }
}

// ---------------- core 32-ic accumulation: 3px x 8oc (4 pairs) ----------------
__device__ __forceinline__ void conv_accum32(
    const float* s_w, const float* s_in, int l, int oc0, ull acc[3][4])
{
    for (int ic = 0; ic < 32; ic++) {
        ull rf[3][5];
#pragma unroll
        for (int r = 0; r < 3; r++) {
            const float* fp = s_in + (r*32 + ic)*99 + 3*l;
#pragma unroll
            for (int t = 0; t < 5; t++) rf[r][t] = rep2(fp[t]);
        }
#pragma unroll
        for (int ky = 0; ky < 3; ky++)
#pragma unroll
        for (int kx = 0; kx < 3; kx++) {
            const ulonglong2* wp =
                (const ulonglong2*)(s_w + ((ky*3 + kx)*32 + ic)*64 + oc0);
            ulonglong2 wA = wp[0];
            ulonglong2 wB = wp[1];
#pragma unroll
            for (int p = 0; p < 3; p++) {
                ull f = rf[ky][p + kx];
                ffma2(acc[p][0], f, wA.x);
                ffma2(acc[p][1], f, wA.y);
                ffma2(acc[p][2], f, wB.x);
                ffma2(acc[p][3], f, wB.y);
            }
        }
    }
}

// =================================================================
// coord_conv: 258ic -> 64oc, 3x3, +bias, BN1, ReLU. grid (96, 8), block 256
// =================================================================
__global__ void __launch_bounds__(256, 2) k_coordn(
    const float* __restrict__ feat, const float* __restrict__ cb,
    const float* __restrict__ bg, const float* __restrict__ bbx,
    const float* __restrict__ bm, const float* __restrict__ bv)
{
    extern __shared__ float sm[];
    float* s_w     = sm;              // [9][32][64] (reused as s_cw in tail)
    float* s_in    = s_w + 9*32*64;   // [3][32][99]
    float* s_scale = s_in + 3*32*99;  // [64]
    float* s_shift = s_scale + 64;    // [64]

    int tid = threadIdx.x;
    int l   = tid & 31;
    int w   = tid >> 5;
    int oc0 = w * 8;
    int y   = blockIdx.x;
    int b   = blockIdx.y;

    if (tid < 64) {
        float inv = bg[tid] / sqrtf(bv[tid] + EPSV);
        s_scale[tid] = inv;
        s_shift[tid] = cb[tid]*inv + (bbx[tid] - bm[tid]*inv);
    }

    ull acc[3][4];
#pragma unroll
    for (int p = 0; p < 3; p++)
#pragma unroll
    for (int j = 0; j < 4; j++) acc[p][j] = 0ULL;

    for (int chunk = 0; chunk < 8; chunk++) {
        __syncthreads();
        load_tile_w(g_wc, 258, chunk*32, s_w, tid, 256);
        load_tile_in(feat, C0, chunk*32, s_in, y, b, tid, 256);
        __syncthreads();
        conv_accum32(s_w, s_in, l, oc0, acc);
    }

    // tail: coord channels (ic 256=xx, 257=yy) — reuse s_w space
    __syncthreads();
    float* s_cw = s_w;   // [9][2][64]
    for (int e = tid; e < 9*2*64; e += 256) {
        int oc  = e & 63;
        int cc  = (e >> 6) & 1;
        int tap = e >> 7;
        s_cw[e] = g_wc[(tap*258 + 256 + cc)*64 + oc];
    }
    __syncthreads();

#pragma unroll
    for (int p = 0; p < 3; p++) {
        int px = 3*l + p;
        float a[8];
        a[0]=lo2(acc[p][0]); a[1]=hi2(acc[p][0]);
        a[2]=lo2(acc[p][1]); a[3]=hi2(acc[p][1]);
        a[4]=lo2(acc[p][2]); a[5]=hi2(acc[p][2]);
        a[6]=lo2(acc[p][3]); a[7]=hi2(acc[p][3]);
#pragma unroll
        for (int tap = 0; tap < 9; tap++) {
            int gy = y + tap/3 - 1;
            int gx = px + tap%3 - 1;
            if ((unsigned)gy < HH && (unsigned)gx < WW) {
                float cx = -1.f + (float)gx * (2.f/95.f);  // ic 256
                float cy = -1.f + (float)gy * (2.f/95.f);  // ic 257
#pragma unroll
                for (int j = 0; j < 8; j++)
                    a[j] += s_cw[tap*128 + oc0 + j]*cx
                          + s_cw[tap*128 + 64 + oc0 + j]*cy;
            }
        }
        float o[8];
#pragma unroll
        for (int j = 0; j < 8; j++)
            o[j] = fmaxf(a[j]*s_scale[oc0+j] + s_shift[oc0+j], 0.f);
        float* outp = g_x1 + ((b*HH + y)*WW + px)*HD + oc0;
        *(float4*)outp       = make_float4(o[0], o[1], o[2], o[3]);
        *(float4*)(outp + 4) = make_float4(o[4], o[5], o[6], o[7]);
    }
}

// =================================================================
// plain 3x3 conv 64->64 + BN + ReLU. grid (96, 8), block 256
// =================================================================
__global__ void __launch_bounds__(256, 2) k_conv3n(
    const float* __restrict__ in, float* __restrict__ out,
    const float* __restrict__ gw,
    const float* __restrict__ bg, const float* __restrict__ bbx,
    const float* __restrict__ bm, const float* __restrict__ bv)
{
    extern __shared__ float sm[];
    float* s_w     = sm;
    float* s_in    = s_w + 9*32*64;
    float* s_scale = s_in + 3*32*99;
    float* s_shift = s_scale + 64;

    int tid = threadIdx.x;
    int l   = tid & 31;
    int w   = tid >> 5;
    int oc0 = w * 8;
    int y   = blockIdx.x;
    int b   = blockIdx.y;

    if (tid < 64) {
        float inv = bg[tid] / sqrtf(bv[tid] + EPSV);
        s_scale[tid] = inv;
        s_shift[tid] = bbx[tid] - bm[tid]*inv;
    }

    ull acc[3][4];
#pragma unroll
    for (int p = 0; p < 3; p++)
#pragma unroll
    for (int j = 0; j < 4; j++) acc[p][j] = 0ULL;

    for (int chunk = 0; chunk < 2; chunk++) {
        __syncthreads();
        load_tile_w(gw, 64, chunk*32, s_w, tid, 256);
        load_tile_in(in, HD, chunk*32, s_in, y, b, tid, 256);
        __syncthreads();
        conv_accum32(s_w, s_in, l, oc0, acc);
    }

#pragma unroll
    for (int p = 0; p < 3; p++) {
        int px = 3*l + p;
        float a[8];
        a[0]=lo2(acc[p][0]); a[1]=hi2(acc[p][0]);
        a[2]=lo2(acc[p][1]); a[3]=hi2(acc[p][1]);
        a[4]=lo2(acc[p][2]); a[5]=hi2(acc[p][2]);
        a[6]=lo2(acc[p][3]); a[7]=hi2(acc[p][3]);
        float o[8];
#pragma unroll
        for (int j = 0; j < 8; j++)
            o[j] = fmaxf(a[j]*s_scale[oc0+j] + s_shift[oc0+j], 0.f);
        float* outp = out + ((b*HH + y)*WW + px)*HD + oc0;
        *(float4*)outp       = make_float4(o[0], o[1], o[2], o[3]);
        *(float4*)(outp + 4) = make_float4(o[4], o[5], o[6], o[7]);
    }
}

// =================================================================
// offset conv: 64ic -> 18oc, 3x3, +bias. grid (96, 8), block 288
// =================================================================
__global__ void __launch_bounds__(288, 2) k_offc(const float* __restrict__ bias)
{
    extern __shared__ float sm[];
    float* s_w  = sm;               // [9][32][18] = 5184
    float* s_in = s_w + 9*32*18;    // [3][32][99]

    int tid = threadIdx.x;
    int l   = tid & 31;
    int w   = tid >> 5;             // 0..8
    int y   = blockIdx.x;
    int b   = blockIdx.y;

    float acc[3][2];
#pragma unroll
    for (int p = 0; p < 3; p++) { acc[p][0] = 0.f; acc[p][1] = 0.f; }

    for (int chunk = 0; chunk < 2; chunk++) {
        __syncthreads();
        for (int e = tid; e < 9*32*18; e += 288) {
            int tap = e / 576;
            int rem = e % 576;          // ic*18 + oc
            s_w[e] = g_wo[tap*1152 + chunk*32*18 + rem];
        }
        load_tile_in(g_x1, HD, chunk*32, s_in, y, b, tid, 288);
        __syncthreads();

        for (int ic = 0; ic < 32; ic++) {
            float f[3][5];
#pragma unroll
            for (int r = 0; r < 3; r++) {
                const float* fp = s_in + (r*32 + ic)*99 + 3*l;
#pragma unroll
                for (int t = 0; t < 5; t++) f[r][t] = fp[t];
            }
#pragma unroll
            for (int ky = 0; ky < 3; ky++)
#pragma unroll
            for (int kx = 0; kx < 3; kx++) {
                float2 wv = *(const float2*)(s_w + ((ky*3+kx)*32 + ic)*18 + 2*w);
#pragma unroll
                for (int p = 0; p < 3; p++) {
                    acc[p][0] += f[ky][p+kx]*wv.x;
                    acc[p][1] += f[ky][p+kx]*wv.y;
                }
            }
        }
    }

    float b0 = __ldg(&bias[2*w]);
    float b1 = __ldg(&bias[2*w + 1]);
#pragma unroll
    for (int p = 0; p < 3; p++) {
        int px = 3*l + p;
        float2 o = make_float2(acc[p][0] + b0, acc[p][1] + b1);
        *(float2*)(g_off + ((b*HH + y)*WW + px)*18 + 2*w) = o;
    }
}

// =================================================================
// deformable conv v2 (64->64, K=9) + BN2 + ReLU
// grid (3, 96, 8): 32-px row tiles, block 256, 2 CTAs/SM.
// Chunked by tap-triples: s_w [3][64][64], s_acc [3][32px][65ch] (pad-65
// => conflict-free STS by channel AND conflict-free LDS by pixel).
// GEMM: thread = (px=lane, 8 oc = 4 f32x2 pairs), FFMA2 inner loop.
// =================================================================
__global__ void __launch_bounds__(256, 2) k_deform(
    const float* __restrict__ bg, const float* __restrict__ bbx,
    const float* __restrict__ bm, const float* __restrict__ bv)
{
    extern __shared__ float sm[];
    float* s_w     = sm;                    // [3][64][64] = 12288
    float* s_acc   = s_w + 3*64*64;         // [3][32][65] = 6240
    float* s_off   = s_acc + 3*32*65;       // [32][18]    = 576
    float* s_scale = s_off + 32*18;         // [64]
    float* s_shift = s_scale + 64;          // [64]

    int tid = threadIdx.x;
    int xb  = blockIdx.x * 32;
    int y   = blockIdx.y;
    int b   = blockIdx.z;

    // gather mapping: channel on lanes (coalesced LDG), 4 groups x 8 px
    int c   = tid & 63;
    int pg  = tid >> 6;
    // gemm mapping: px on lanes, warp -> 8 oc
    int l   = tid & 31;
    int oc0 = (tid >> 5) * 8;

    for (int e = tid; e < 32*18; e += 256) {
        int px = e / 18, j = e % 18;
        s_off[e] = g_off[((b*HH + y)*WW + xb + px)*18 + j];
    }
    if (tid < 64) {
        float inv = bg[tid] / sqrtf(bv[tid] + EPSV);
        s_scale[tid] = inv;
        s_shift[tid] = bbx[tid] - bm[tid]*inv;
    }

    ull acc[4] = {0ULL, 0ULL, 0ULL, 0ULL};
    const float* base = g_x1 + (size_t)b*HH*WW*HD + c;

    for (int kc = 0; kc < 3; kc++) {
        __syncthreads();
        // weights for taps kc*3 .. kc*3+2 : contiguous in g_wd
        {
            const float4* src = (const float4*)(g_wd + kc*3*64*64);
            for (int e = tid; e < 3*64*64/4; e += 256)
                ((float4*)s_w)[e] = src[e];
        }
        // bilinear gather for 3 taps x 32 px (this thread: 8 px, all 3 taps)
#pragma unroll
        for (int kk = 0; kk < 3; kk++) {
            int k = kc*3 + kk;
            float koy = (float)(k/3 - 1);
            float kox = (float)(k%3 - 1);
#pragma unroll
            for (int i = 0; i < 8; i++) {
                int px = pg*8 + i;
                int x  = xb + px;
                float py  = (float)y + koy + s_off[px*18 + 2*k];
                float pxf = (float)x + kox + s_off[px*18 + 2*k + 1];
                float fy0 = floorf(py), fx0 = floorf(pxf);
                int  iy = (int)fy0, ix = (int)fx0;
                float fy = py - fy0, fx = pxf - fx0;
                float a = 0.f;
                if ((unsigned)iy < HH) {
                    const float* row = base + iy*(WW*HD);
                    if ((unsigned)ix < WW)     a += row[ix*HD]     * (1.f-fy)*(1.f-fx);
                    if ((unsigned)(ix+1) < WW) a += row[(ix+1)*HD] * (1.f-fy)*fx;
                }
                if ((unsigned)(iy+1) < HH) {
                    const float* row = base + (iy+1)*(WW*HD);
                    if ((unsigned)ix < WW)     a += row[ix*HD]     * fy*(1.f-fx);
                    if ((unsigned)(ix+1) < WW) a += row[(ix+1)*HD] * fy*fx;
                }
                s_acc[(kk*32 + px)*65 + c] = a;
            }
        }
        __syncthreads();

        // GEMM: this thread: px=l, oc pairs oc0/2 .. oc0/2+3
#pragma unroll
        for (int kk = 0; kk < 3; kk++) {
            const float* ap = s_acc + (kk*32 + l)*65;
            const float* wb = s_w + kk*64*64 + oc0;
#pragma unroll 16
            for (int ic = 0; ic < 64; ic++) {
                ull f = rep2(ap[ic]);
                const ulonglong2* wp = (const ulonglong2*)(wb + ic*64);
                ulonglong2 wA = wp[0];
                ulonglong2 wB = wp[1];
                ffma2(acc[0], f, wA.x);
                ffma2(acc[1], f, wA.y);
                ffma2(acc[2], f, wB.x);
                ffma2(acc[3], f, wB.y);
            }
        }
    }

    float a[8];
    a[0]=lo2(acc[0]); a[1]=hi2(acc[0]);
    a[2]=lo2(acc[1]); a[3]=hi2(acc[1]);
    a[4]=lo2(acc[2]); a[5]=hi2(acc[2]);
    a[6]=lo2(acc[3]); a[7]=hi2(acc[3]);
    float o[8];
#pragma unroll
    for (int j = 0; j < 8; j++)
        o[j] = fmaxf(a[j]*s_scale[oc0+j] + s_shift[oc0+j], 0.f);
    float* outp = g_x2 + ((size_t)(b*HH + y)*WW + xb + l)*HD + oc0;
    *(float4*)outp       = make_float4(o[0], o[1], o[2], o[3]);
    *(float4*)(outp + 4) = make_float4(o[4], o[5], o[6], o[7]);
}

// =================================================================
// 1x1 conv (64->1) + sigmoid
// =================================================================
__global__ void __launch_bounds__(256) k_out(
    const float* __restrict__ ow, const float* __restrict__ ob,
    float* __restrict__ outp)
{
    __shared__ float sw[64];
    __shared__ float sb0;
    int tid = threadIdx.x;
    if (tid < 64) sw[tid] = ow[tid];
    if (tid == 0) sb0 = ob[0];
    __syncthreads();
    int p = blockIdx.x*256 + tid;
    if (p < BB*HH*WW) {
        const float4* xp = (const float4*)(g_x4 + (size_t)p*64);
        const float4* wp = (const float4*)sw;
        float a = 0.f;
#pragma unroll
        for (int i = 0; i < 16; i++) {
            float4 xv = xp[i], wv = wp[i];
            a += xv.x*wv.x + xv.y*wv.y + xv.z*wv.z + xv.w*wv.w;
        }
        outp[p] = 1.f / (1.f + expf(-(a + sb0)));
    }
}

// =================================================================
extern "C" void kernel_launch(void* const* d_in, const int* in_sizes, int n_in,
                              void* d_out, int out_size)
{
    const float* feat    = (const float*)d_in[0];
    const float* coord_w = (const float*)d_in[1];
    const float* coord_b = (const float*)d_in[2];
    const float* bn1_g   = (const float*)d_in[3];
    const float* bn1_b   = (const float*)d_in[4];
    const float* bn1_m   = (const float*)d_in[5];
    const float* bn1_v   = (const float*)d_in[6];
    const float* off_w   = (const float*)d_in[7];
    const float* off_b   = (const float*)d_in[8];
    const float* dc_w    = (const float*)d_in[9];
    const float* bn2_g   = (const float*)d_in[10];
    const float* bn2_b   = (const float*)d_in[11];
    const float* bn2_m   = (const float*)d_in[12];
    const float* bn2_v   = (const float*)d_in[13];
    const float* r1_w    = (const float*)d_in[14];
    const float* bn3_g   = (const float*)d_in[15];
    const float* bn3_b   = (const float*)d_in[16];
    const float* bn3_m   = (const float*)d_in[17];
    const float* bn3_v   = (const float*)d_in[18];
    const float* r2_w    = (const float*)d_in[19];
    const float* bn4_g   = (const float*)d_in[20];
    const float* bn4_b   = (const float*)d_in[21];
    const float* bn4_m   = (const float*)d_in[22];
    const float* bn4_v   = (const float*)d_in[23];
    const float* out_w   = (const float*)d_in[24];
    const float* out_b   = (const float*)d_in[25];
    float* out = (float*)d_out;

    const int SM_CONV = (9*32*64 + 3*32*99 + 128) * 4;            // 112256
    const int SM_OFF  = (9*32*18 + 3*32*99) * 4;                  // 58752
    const int SMD     = (3*64*64 + 3*32*65 + 32*18 + 128) * 4;    // 76928

    cudaFuncSetAttribute(k_coordn, cudaFuncAttributeMaxDynamicSharedMemorySize, SM_CONV);
    cudaFuncSetAttribute(k_conv3n, cudaFuncAttributeMaxDynamicSharedMemorySize, SM_CONV);
    cudaFuncSetAttribute(k_offc,   cudaFuncAttributeMaxDynamicSharedMemorySize, SM_OFF);
    cudaFuncSetAttribute(k_deform, cudaFuncAttributeMaxDynamicSharedMemorySize, SMD);

    void *px2 = nullptr, *px3 = nullptr, *px4 = nullptr;
    cudaGetSymbolAddress(&px2, g_x2);
    cudaGetSymbolAddress(&px3, g_x3);
    cudaGetSymbolAddress(&px4, g_x4);
    void *pw1 = nullptr, *pw2 = nullptr;
    cudaGetSymbolAddress(&pw1, g_w1);
    cudaGetSymbolAddress(&pw2, g_w2);

    k_prep<<<581, 256>>>(coord_w, r1_w, r2_w, dc_w, off_w);

    dim3 gRow(96, 8);
    k_coordn<<<gRow, 256, SM_CONV>>>(feat, coord_b, bn1_g, bn1_b, bn1_m, bn1_v);
    k_offc<<<gRow, 288, SM_OFF>>>(off_b);
    k_deform<<<dim3(3, 96, 8), 256, SMD>>>(bn2_g, bn2_b, bn2_m, bn2_v);
    k_conv3n<<<gRow, 256, SM_CONV>>>((const float*)px2, (float*)px3,
                                     (const float*)pw1, bn3_g, bn3_b, bn3_m, bn3_v);
    k_conv3n<<<gRow, 256, SM_CONV>>>((const float*)px3, (float*)px4,
                                     (const float*)pw2, bn4_g, bn4_b, bn4_m, bn4_v);
    k_out<<<288, 256>>>(out_w, out_b, out);
}

// round 11
// speedup vs baseline: 4.2288x; 1.1072x over previous
#include <cuda_runtime.h>
#include <math.h>

#define BB 8
#define HH 96
#define WW 96
#define C0 256
#define HD 64
#define EPSV 1e-5f

typedef unsigned long long ull;

// ---------------- scratch (no allocations allowed) ----------------
__device__ float g_x1[BB*HH*WW*HD];    // after coordconv+bn1+relu (NHWC)
__device__ float g_off[BB*HH*WW*18];   // offsets (NHWC, c=18)
__device__ float g_acc[(size_t)BB*HH*WW*9*64]; // bilinear-gathered [px][9][64]
__device__ float g_x2[BB*HH*WW*HD];    // after deform+bn2+relu
__device__ float g_x3[BB*HH*WW*HD];    // after r1+bn3+relu
__device__ float g_x4[BB*HH*WW*HD];    // after r2+bn4+relu

// transposed weights [tap][ic][oc]
__device__ float g_wc[9*258*64];       // coord_w
__device__ float g_w1[9*64*64];        // r1_w
__device__ float g_w2[9*64*64];        // r2_w
__device__ float g_wd[9*64*64];        // dc_w ([k][ic][oc])
__device__ float g_wo[9*64*18];        // off_w

// ---------------- f32x2 helpers ----------------
__device__ __forceinline__ void ffma2(ull &d, ull a, ull b) {
    asm("fma.rn.f32x2 %0, %1, %2, %0;" : "+l"(d) : "l"(a), "l"(b));
}
__device__ __forceinline__ ull rep2(float v) {
    unsigned u = __float_as_uint(v);
    ull r;
    asm("mov.b64 %0, {%1, %1};" : "=l"(r) : "r"(u));
    return r;
}
__device__ __forceinline__ float lo2(ull u) { return __uint_as_float((unsigned)u); }
__device__ __forceinline__ float hi2(ull u) { return __uint_as_float((unsigned)(u >> 32)); }

// =================================================================
// weight transpose prep (runs once per launch, cheap)
// =================================================================
__global__ void k_prep(const float* __restrict__ cw, const float* __restrict__ r1,
                       const float* __restrict__ r2, const float* __restrict__ dc,
                       const float* __restrict__ ow)
{
    int i = blockIdx.x*256 + threadIdx.x;
    if (i < 9*258*64) {
        int oc = i & 63; int ic = (i >> 6) % 258; int tap = i / (258*64);
        g_wc[i] = cw[(oc*258 + ic)*9 + tap];
    }
    if (i < 9*64*64) {
        int oc = i & 63; int ic = (i >> 6) & 63; int tap = i >> 12;
        g_w1[i] = r1[(oc*64 + ic)*9 + tap];
        g_w2[i] = r2[(oc*64 + ic)*9 + tap];
        g_wd[i] = dc[(oc*64 + ic)*9 + tap];
    }
    if (i < 9*64*18) {
        int oc = i % 18; int ic = (i/18) & 63; int tap = i / (18*64);
        g_wo[i] = ow[(oc*64 + ic)*9 + tap];
    }
}

// ---------------- shared loaders (16-ic chunk) ----------------
// s_in layout: [3 rows][16 ic][99]
__device__ __forceinline__ void load_tile_in16(
    const float* __restrict__ gsrc, int Cstride, int ic0,
    float* s_in, int y, int b, int tid, int nthreads)
{
    for (int e = tid; e < 3*98*16; e += nthreads) {
        int ic = e & 15;
        int p  = (e >> 4) % 98;
        int r  = e / (98*16);
        int gy = y + r - 1, gx = p - 1;
        float v = 0.f;
        if ((unsigned)gy < HH && (unsigned)gx < WW)
            v = gsrc[((b*HH + gy)*WW + gx)*Cstride + ic0 + ic];
        s_in[(r*16 + ic)*99 + p] = v;
    }
}

// s_w layout: [9 tap][16 ic][64 oc]; gw layout [9][ICTOT][64]
__device__ __forceinline__ void load_tile_w16(
    const float* __restrict__ gw, int ICTOT, int ic0,
    float* s_w, int tid, int nthreads)
{
    const int N4 = 9*16*64/4;  // 2304 float4
    for (int e = tid; e < N4; e += nthreads) {
        int oc4 = (e & 15) * 4;
        int ic  = (e >> 4) & 15;
        int tap = e >> 8;
        *(float4*)(s_w + (tap*16 + ic)*64 + oc4) =
            *(const float4*)(gw + (tap*ICTOT + ic0 + ic)*64 + oc4);
    }
}

// 32-ic input loader kept for offc
__device__ __forceinline__ void load_tile_in32(
    const float* __restrict__ gsrc, int Cstride, int ic0,
    float* s_in, int y, int b, int tid, int nthreads)
{
    for (int e = tid; e < 3*98*32; e += nthreads) {
        int ic = e & 31;
        int p  = (e >> 5) % 98;
        int r  = e / (98*32);
        int gy = y + r - 1, gx = p - 1;
        float v = 0.f;
        if ((unsigned)gy < HH && (unsigned)gx < WW)
            v = gsrc[((b*HH + gy)*WW + gx)*Cstride + ic0 + ic];
        s_in[(r*32 + ic)*99 + p] = v;
    }
}

// ---------------- core 16-ic accumulation: 3px x 8oc (4 pairs) ----------------
// rf held per-ky only -> ~20 fewer live registers than rf[3][5] variant
__device__ __forceinline__ void conv_accum16(
    const float* s_w, const float* s_in, int l, int oc0, ull acc[3][4])
{
    for (int ic = 0; ic < 16; ic++) {
#pragma unroll
        for (int ky = 0; ky < 3; ky++) {
            ull rf[5];
            const float* fp = s_in + (ky*16 + ic)*99 + 3*l;
#pragma unroll
            for (int t = 0; t < 5; t++) rf[t] = rep2(fp[t]);
#pragma unroll
            for (int kx = 0; kx < 3; kx++) {
                const ulonglong2* wp =
                    (const ulonglong2*)(s_w + ((ky*3 + kx)*16 + ic)*64 + oc0);
                ulonglong2 wA = wp[0];
                ulonglong2 wB = wp[1];
#pragma unroll
                for (int p = 0; p < 3; p++) {
                    ull f = rf[p + kx];
                    ffma2(acc[p][0], f, wA.x);
                    ffma2(acc[p][1], f, wA.y);
                    ffma2(acc[p][2], f, wB.x);
                    ffma2(acc[p][3], f, wB.y);
                }
            }
        }
    }
}

// =================================================================
// coord_conv: 258ic -> 64oc, 3x3, +bias, BN1, ReLU. grid (96, 8), block 256
// smem 56KB -> 3 CTAs/SM
// =================================================================
__global__ void __launch_bounds__(256, 3) k_coordn(
    const float* __restrict__ feat, const float* __restrict__ cb,
    const float* __restrict__ bg, const float* __restrict__ bbx,
    const float* __restrict__ bm, const float* __restrict__ bv)
{
    extern __shared__ float sm[];
    float* s_w     = sm;               // [9][16][64] (reused as s_cw in tail)
    float* s_in    = s_w + 9*16*64;    // [3][16][99]
    float* s_scale = s_in + 3*16*99;   // [64]
    float* s_shift = s_scale + 64;     // [64]

    int tid = threadIdx.x;
    int l   = tid & 31;
    int oc0 = (tid >> 5) * 8;
    int y   = blockIdx.x;
    int b   = blockIdx.y;

    if (tid < 64) {
        float inv = bg[tid] / sqrtf(bv[tid] + EPSV);
        s_scale[tid] = inv;
        s_shift[tid] = cb[tid]*inv + (bbx[tid] - bm[tid]*inv);
    }

    ull acc[3][4];
#pragma unroll
    for (int p = 0; p < 3; p++)
#pragma unroll
    for (int j = 0; j < 4; j++) acc[p][j] = 0ULL;

    for (int chunk = 0; chunk < 16; chunk++) {
        __syncthreads();
        load_tile_w16(g_wc, 258, chunk*16, s_w, tid, 256);
        load_tile_in16(feat, C0, chunk*16, s_in, y, b, tid, 256);
        __syncthreads();
        conv_accum16(s_w, s_in, l, oc0, acc);
    }

    // tail: coord channels (ic 256=xx, 257=yy) — reuse s_w space
    __syncthreads();
    float* s_cw = s_w;   // [9][2][64]
    for (int e = tid; e < 9*2*64; e += 256) {
        int oc  = e & 63;
        int cc  = (e >> 6) & 1;
        int tap = e >> 7;
        s_cw[e] = g_wc[(tap*258 + 256 + cc)*64 + oc];
    }
    __syncthreads();

#pragma unroll
    for (int p = 0; p < 3; p++) {
        int px = 3*l + p;
        float a[8];
        a[0]=lo2(acc[p][0]); a[1]=hi2(acc[p][0]);
        a[2]=lo2(acc[p][1]); a[3]=hi2(acc[p][1]);
        a[4]=lo2(acc[p][2]); a[5]=hi2(acc[p][2]);
        a[6]=lo2(acc[p][3]); a[7]=hi2(acc[p][3]);
#pragma unroll
        for (int tap = 0; tap < 9; tap++) {
            int gy = y + tap/3 - 1;
            int gx = px + tap%3 - 1;
            if ((unsigned)gy < HH && (unsigned)gx < WW) {
                float cx = -1.f + (float)gx * (2.f/95.f);  // ic 256
                float cy = -1.f + (float)gy * (2.f/95.f);  // ic 257
#pragma unroll
                for (int j = 0; j < 8; j++)
                    a[j] += s_cw[tap*128 + oc0 + j]*cx
                          + s_cw[tap*128 + 64 + oc0 + j]*cy;
            }
        }
        float o[8];
#pragma unroll
        for (int j = 0; j < 8; j++)
            o[j] = fmaxf(a[j]*s_scale[oc0+j] + s_shift[oc0+j], 0.f);
        float* outp = g_x1 + ((b*HH + y)*WW + px)*HD + oc0;
        *(float4*)outp       = make_float4(o[0], o[1], o[2], o[3]);
        *(float4*)(outp + 4) = make_float4(o[4], o[5], o[6], o[7]);
    }
}

// =================================================================
// plain 3x3 conv 64->64 + BN + ReLU. grid (96, 8), block 256, 3 CTAs/SM
// =================================================================
__global__ void __launch_bounds__(256, 3) k_conv3n(
    const float* __restrict__ in, float* __restrict__ out,
    const float* __restrict__ gw,
    const float* __restrict__ bg, const float* __restrict__ bbx,
    const float* __restrict__ bm, const float* __restrict__ bv)
{
    extern __shared__ float sm[];
    float* s_w     = sm;
    float* s_in    = s_w + 9*16*64;
    float* s_scale = s_in + 3*16*99;
    float* s_shift = s_scale + 64;

    int tid = threadIdx.x;
    int l   = tid & 31;
    int oc0 = (tid >> 5) * 8;
    int y   = blockIdx.x;
    int b   = blockIdx.y;

    if (tid < 64) {
        float inv = bg[tid] / sqrtf(bv[tid] + EPSV);
        s_scale[tid] = inv;
        s_shift[tid] = bbx[tid] - bm[tid]*inv;
    }

    ull acc[3][4];
#pragma unroll
    for (int p = 0; p < 3; p++)
#pragma unroll
    for (int j = 0; j < 4; j++) acc[p][j] = 0ULL;

    for (int chunk = 0; chunk < 4; chunk++) {
        __syncthreads();
        load_tile_w16(gw, 64, chunk*16, s_w, tid, 256);
        load_tile_in16(in, HD, chunk*16, s_in, y, b, tid, 256);
        __syncthreads();
        conv_accum16(s_w, s_in, l, oc0, acc);
    }

#pragma unroll
    for (int p = 0; p < 3; p++) {
        int px = 3*l + p;
        float a[8];
        a[0]=lo2(acc[p][0]); a[1]=hi2(acc[p][0]);
        a[2]=lo2(acc[p][1]); a[3]=hi2(acc[p][1]);
        a[4]=lo2(acc[p][2]); a[5]=hi2(acc[p][2]);
        a[6]=lo2(acc[p][3]); a[7]=hi2(acc[p][3]);
        float o[8];
#pragma unroll
        for (int j = 0; j < 8; j++)
            o[j] = fmaxf(a[j]*s_scale[oc0+j] + s_shift[oc0+j], 0.f);
        float* outp = out + ((b*HH + y)*WW + px)*HD + oc0;
        *(float4*)outp       = make_float4(o[0], o[1], o[2], o[3]);
        *(float4*)(outp + 4) = make_float4(o[4], o[5], o[6], o[7]);
    }
}

// =================================================================
// offset conv: 64ic -> 18oc, 3x3, +bias. grid (96, 8), block 288
// =================================================================
__global__ void __launch_bounds__(288, 2) k_offc(const float* __restrict__ bias)
{
    extern __shared__ float sm[];
    float* s_w  = sm;               // [9][32][18] = 5184
    float* s_in = s_w + 9*32*18;    // [3][32][99]

    int tid = threadIdx.x;
    int l   = tid & 31;
    int w   = tid >> 5;             // 0..8
    int y   = blockIdx.x;
    int b   = blockIdx.y;

    float acc[3][2];
#pragma unroll
    for (int p = 0; p < 3; p++) { acc[p][0] = 0.f; acc[p][1] = 0.f; }

    for (int chunk = 0; chunk < 2; chunk++) {
        __syncthreads();
        for (int e = tid; e < 9*32*18; e += 288) {
            int tap = e / 576;
            int rem = e % 576;          // ic*18 + oc
            s_w[e] = g_wo[tap*1152 + chunk*32*18 + rem];
        }
        load_tile_in32(g_x1, HD, chunk*32, s_in, y, b, tid, 288);
        __syncthreads();

        for (int ic = 0; ic < 32; ic++) {
            float f[3][5];
#pragma unroll
            for (int r = 0; r < 3; r++) {
                const float* fp = s_in + (r*32 + ic)*99 + 3*l;
#pragma unroll
                for (int t = 0; t < 5; t++) f[r][t] = fp[t];
            }
#pragma unroll
            for (int ky = 0; ky < 3; ky++)
#pragma unroll
            for (int kx = 0; kx < 3; kx++) {
                float2 wv = *(const float2*)(s_w + ((ky*3+kx)*32 + ic)*18 + 2*w);
#pragma unroll
                for (int p = 0; p < 3; p++) {
                    acc[p][0] += f[ky][p+kx]*wv.x;
                    acc[p][1] += f[ky][p+kx]*wv.y;
                }
            }
        }
    }

    float b0 = __ldg(&bias[2*w]);
    float b1 = __ldg(&bias[2*w + 1]);
#pragma unroll
    for (int p = 0; p < 3; p++) {
        int px = 3*l + p;
        float2 o = make_float2(acc[p][0] + b0, acc[p][1] + b1);
        *(float2*)(g_off + ((b*HH + y)*WW + px)*18 + 2*w) = o;
    }
}

// =================================================================
// deform phase A: bilinear gather -> g_acc[px][9][64]
// warp-per-pixel, lane c covers channels {c, c+32}. No smem, high occ.
// grid 9216 x block 256 (8 warps = 8 px per CTA)
// =================================================================
__global__ void __launch_bounds__(256) k_gather()
{
    int warp = threadIdx.x >> 5;
    int lane = threadIdx.x & 31;
    int p = blockIdx.x * 8 + warp;      // global pixel 0..73727
    int b = p / (HH*WW);
    int rem = p - b*(HH*WW);
    int y = rem / WW;
    int x = rem - y*WW;

    const float* offp = g_off + (size_t)p*18;
    const float* base = g_x1 + (size_t)b*HH*WW*HD + lane;
    float* outp = g_acc + (size_t)p*9*64;

#pragma unroll
    for (int k = 0; k < 9; k++) {
        float py  = (float)(y + k/3 - 1) + offp[2*k];
        float pxf = (float)(x + k%3 - 1) + offp[2*k + 1];
        float fy0 = floorf(py), fx0 = floorf(pxf);
        int  iy = (int)fy0, ix = (int)fx0;
        float fy = py - fy0, fx = pxf - fx0;
        float w00 = (1.f-fy)*(1.f-fx), w01 = (1.f-fy)*fx;
        float w10 = fy*(1.f-fx),       w11 = fy*fx;
        float a0 = 0.f, a1 = 0.f;
        if ((unsigned)iy < HH) {
            const float* row = base + iy*(WW*HD);
            if ((unsigned)ix < WW) {
                const float* q = row + ix*HD;
                a0 += q[0]*w00; a1 += q[32]*w00;
            }
            if ((unsigned)(ix+1) < WW) {
                const float* q = row + (ix+1)*HD;
                a0 += q[0]*w01; a1 += q[32]*w01;
            }
        }
        if ((unsigned)(iy+1) < HH) {
            const float* row = base + (iy+1)*(WW*HD);
            if ((unsigned)ix < WW) {
                const float* q = row + ix*HD;
                a0 += q[0]*w10; a1 += q[32]*w10;
            }
            if ((unsigned)(ix+1) < WW) {
                const float* q = row + (ix+1)*HD;
                a0 += q[0]*w11; a1 += q[32]*w11;
            }
        }
        outp[k*64 + lane]      = a0;
        outp[k*64 + lane + 32] = a1;
    }
}

// =================================================================
// deform phase B: GEMM  out[px][64] = acc[px][576] @ w[576][64], +BN2+ReLU
// grid 2304: 32-px tiles, block 256, smem 25KB -> 4 CTAs/SM
// =================================================================
__global__ void __launch_bounds__(256, 4) k_dgemm(
    const float* __restrict__ bg, const float* __restrict__ bbx,
    const float* __restrict__ bm, const float* __restrict__ bv)
{
    extern __shared__ float sm[];
    float* s_w     = sm;                // [64][64]
    float* s_a     = s_w + 64*64;       // [32][65]
    float* s_scale = s_a + 32*65;       // [64]
    float* s_shift = s_scale + 64;      // [64]

    int tid = threadIdx.x;
    int l   = tid & 31;                 // px within tile
    int oc0 = (tid >> 5) * 8;
    int px0 = blockIdx.x * 32;

    if (tid < 64) {
        float inv = bg[tid] / sqrtf(bv[tid] + EPSV);
        s_scale[tid] = inv;
        s_shift[tid] = bbx[tid] - bm[tid]*inv;
    }

    ull acc[4] = {0ULL, 0ULL, 0ULL, 0ULL};

    for (int t = 0; t < 9; t++) {
        __syncthreads();
        {
            const float4* src = (const float4*)(g_wd + t*64*64);
            for (int e = tid; e < 64*64/4; e += 256)
                ((float4*)s_w)[e] = src[e];
        }
        for (int e = tid; e < 32*64; e += 256) {
            int px = e >> 6, ic = e & 63;
            s_a[px*65 + ic] = g_acc[(size_t)(px0 + px)*576 + t*64 + ic];
        }
        __syncthreads();

        const float* ap = s_a + l*65;
        const float* wb = s_w + oc0;
#pragma unroll 16
        for (int ic = 0; ic < 64; ic++) {
            ull f = rep2(ap[ic]);
            const ulonglong2* wp = (const ulonglong2*)(wb + ic*64);
            ulonglong2 wA = wp[0];
            ulonglong2 wB = wp[1];
            ffma2(acc[0], f, wA.x);
            ffma2(acc[1], f, wA.y);
            ffma2(acc[2], f, wB.x);
            ffma2(acc[3], f, wB.y);
        }
    }

    float a[8];
    a[0]=lo2(acc[0]); a[1]=hi2(acc[0]);
    a[2]=lo2(acc[1]); a[3]=hi2(acc[1]);
    a[4]=lo2(acc[2]); a[5]=hi2(acc[2]);
    a[6]=lo2(acc[3]); a[7]=hi2(acc[3]);
    float o[8];
#pragma unroll
    for (int j = 0; j < 8; j++)
        o[j] = fmaxf(a[j]*s_scale[oc0+j] + s_shift[oc0+j], 0.f);
    float* outp = g_x2 + (size_t)(px0 + l)*HD + oc0;
    *(float4*)outp       = make_float4(o[0], o[1], o[2], o[3]);
    *(float4*)(outp + 4) = make_float4(o[4], o[5], o[6], o[7]);
}

// =================================================================
// 1x1 conv (64->1) + sigmoid
// =================================================================
__global__ void __launch_bounds__(256) k_out(
    const float* __restrict__ ow, const float* __restrict__ ob,
    float* __restrict__ outp)
{
    __shared__ float sw[64];
    __shared__ float sb0;
    int tid = threadIdx.x;
    if (tid < 64) sw[tid] = ow[tid];
    if (tid == 0) sb0 = ob[0];
    __syncthreads();
    int p = blockIdx.x*256 + tid;
    if (p < BB*HH*WW) {
        const float4* xp = (const float4*)(g_x4 + (size_t)p*64);
        const float4* wp = (const float4*)sw;
        float a = 0.f;
#pragma unroll
        for (int i = 0; i < 16; i++) {
            float4 xv = xp[i], wv = wp[i];
            a += xv.x*wv.x + xv.y*wv.y + xv.z*wv.z + xv.w*wv.w;
        }
        outp[p] = 1.f / (1.f + expf(-(a + sb0)));
    }
}

// =================================================================
extern "C" void kernel_launch(void* const* d_in, const int* in_sizes, int n_in,
                              void* d_out, int out_size)
{
    const float* feat    = (const float*)d_in[0];
    const float* coord_w = (const float*)d_in[1];
    const float* coord_b = (const float*)d_in[2];
    const float* bn1_g   = (const float*)d_in[3];
    const float* bn1_b   = (const float*)d_in[4];
    const float* bn1_m   = (const float*)d_in[5];
    const float* bn1_v   = (const float*)d_in[6];
    const float* off_w   = (const float*)d_in[7];
    const float* off_b   = (const float*)d_in[8];
    const float* dc_w    = (const float*)d_in[9];
    const float* bn2_g   = (const float*)d_in[10];
    const float* bn2_b   = (const float*)d_in[11];
    const float* bn2_m   = (const float*)d_in[12];
    const float* bn2_v   = (const float*)d_in[13];
    const float* r1_w    = (const float*)d_in[14];
    const float* bn3_g   = (const float*)d_in[15];
    const float* bn3_b   = (const float*)d_in[16];
    const float* bn3_m   = (const float*)d_in[17];
    const float* bn3_v   = (const float*)d_in[18];
    const float* r2_w    = (const float*)d_in[19];
    const float* bn4_g   = (const float*)d_in[20];
    const float* bn4_b   = (const float*)d_in[21];
    const float* bn4_m   = (const float*)d_in[22];
    const float* bn4_v   = (const float*)d_in[23];
    const float* out_w   = (const float*)d_in[24];
    const float* out_b   = (const float*)d_in[25];
    float* out = (float*)d_out;

    const int SM_CONV = (9*16*64 + 3*16*99 + 128) * 4;   // 56384
    const int SM_OFF  = (9*32*18 + 3*32*99) * 4;         // 58752
    const int SM_GEMM = (64*64 + 32*65 + 128) * 4;       // 25216

    cudaFuncSetAttribute(k_coordn, cudaFuncAttributeMaxDynamicSharedMemorySize, SM_CONV);
    cudaFuncSetAttribute(k_conv3n, cudaFuncAttributeMaxDynamicSharedMemorySize, SM_CONV);
    cudaFuncSetAttribute(k_offc,   cudaFuncAttributeMaxDynamicSharedMemorySize, SM_OFF);
    cudaFuncSetAttribute(k_dgemm,  cudaFuncAttributeMaxDynamicSharedMemorySize, SM_GEMM);

    void *px2 = nullptr, *px3 = nullptr, *px4 = nullptr;
    cudaGetSymbolAddress(&px2, g_x2);
    cudaGetSymbolAddress(&px3, g_x3);
    cudaGetSymbolAddress(&px4, g_x4);
    void *pw1 = nullptr, *pw2 = nullptr;
    cudaGetSymbolAddress(&pw1, g_w1);
    cudaGetSymbolAddress(&pw2, g_w2);

    k_prep<<<581, 256>>>(coord_w, r1_w, r2_w, dc_w, off_w);

    dim3 gRow(96, 8);
    k_coordn<<<gRow, 256, SM_CONV>>>(feat, coord_b, bn1_g, bn1_b, bn1_m, bn1_v);
    k_offc<<<gRow, 288, SM_OFF>>>(off_b);
    k_gather<<<9216, 256>>>();
    k_dgemm<<<2304, 256, SM_GEMM>>>(bn2_g, bn2_b, bn2_m, bn2_v);
    k_conv3n<<<gRow, 256, SM_CONV>>>((const float*)px2, (float*)px3,
                                     (const float*)pw1, bn3_g, bn3_b, bn3_m, bn3_v);
    k_conv3n<<<gRow, 256, SM_CONV>>>((const float*)px3, (float*)px4,
                                     (const float*)pw2, bn4_g, bn4_b, bn4_m, bn4_v);
    k_out<<<288, 256>>>(out_w, out_b, out);
}